// round 12
// baseline (speedup 1.0000x reference)
#include <cuda_runtime.h>
#include <cuda_bf16.h>
#include <cuda_fp16.h>
#include <cstdint>

// Problem constants (fixed by the dataset)
#define N_NODES    100000
#define N_FEAT     512
#define N_HID      256
#define ELL_W      128          // slots per row; deg ~ Poisson(32), P(overflow) < 1e-30

// ---------------------------------------------------------------------------
// Static device scratch (no allocations allowed)
// ---------------------------------------------------------------------------
__device__ __align__(16) __half g_xh[(size_t)N_NODES * N_FEAT];     // 102.4 MB
__device__ __align__(16) __half g_hh[(size_t)N_NODES * N_HID];      // 51.2 MB
__device__ __align__(16) __half g_wh[(size_t)N_HID * N_FEAT];       // 256 KB
__device__ int  g_cnt[N_NODES];                                     // 400 KB
__device__ __align__(16) int2 g_eell[(size_t)N_NODES * ELL_W];      // 102.4 MB

// ---------------------------------------------------------------------------
// Baseline-PTX helpers (plain sm_80+; harness targets compute_103 w/o 'a')
// ---------------------------------------------------------------------------
__device__ __forceinline__ uint32_t smem_to_u32(const void* smem_ptr) {
    uint32_t addr;
    asm("{ .reg .u64 tmp; cvta.to.shared.u64 tmp, %1; cvt.u32.u64 %0, tmp; }"
        : "=r"(addr) : "l"(smem_ptr));
    return addr;
}

__device__ __forceinline__ void cp_async16(uint32_t saddr, const void* gptr) {
    asm volatile("cp.async.cg.shared.global [%0], [%1], 16;"
                 :: "r"(saddr), "l"(gptr));
}
#define CP_COMMIT()  asm volatile("cp.async.commit_group;")
#define CP_WAIT(N)   asm volatile("cp.async.wait_group %0;" :: "n"(N))

__device__ __forceinline__ void ldm_x4(uint32_t* r, uint32_t addr) {
    asm volatile("ldmatrix.sync.aligned.m8n8.x4.shared.b16 {%0,%1,%2,%3}, [%4];"
                 : "=r"(r[0]), "=r"(r[1]), "=r"(r[2]), "=r"(r[3]) : "r"(addr));
}

// HMMA m16n8k16 fp16 -> fp32, accumulate in place
__device__ __forceinline__ void mma16816(float* d, const uint32_t* a,
                                         const uint32_t* b) {
    asm volatile(
        "mma.sync.aligned.m16n8k16.row.col.f32.f16.f16.f32 "
        "{%0,%1,%2,%3}, {%4,%5,%6,%7}, {%8,%9}, {%0,%1,%2,%3};"
        : "+f"(d[0]), "+f"(d[1]), "+f"(d[2]), "+f"(d[3])
        : "r"(a[0]), "r"(a[1]), "r"(a[2]), "r"(a[3]),
          "r"(b[0]), "r"(b[1]));
}

__device__ __forceinline__ uint32_t pack_h2(float a, float b) {
    __half2 h = __floats2half2_rn(a, b);
    return *reinterpret_cast<uint32_t*>(&h);
}
__device__ __forceinline__ float2 h2f(uint32_t u) {
    __half2 h = *reinterpret_cast<__half2*>(&u);
    return __half22float2(h);
}

// ---------------------------------------------------------------------------
// Kernel A: fp32 -> fp16 convert (used for W and for x)
// ---------------------------------------------------------------------------
__global__ __launch_bounds__(256)
void f2h_kernel(const float* __restrict__ src, __half* __restrict__ dst,
                int n4)
{
    int i = blockIdx.x * blockDim.x + threadIdx.x;
    if (i >= n4) return;
    float4 v = ((const float4*)src)[i];
    uint2 o;
    o.x = pack_h2(v.x, v.y);
    o.y = pack_h2(v.z, v.w);
    ((uint2*)dst)[i] = o;
}

// ---------------------------------------------------------------------------
// Kernel B: pure-fp16 mma.sync GEMM with bias, fp16 output.
// C[M,256] = Ah * Wh^T + bias.  Tile 128x256x64, 512 threads (4x4 warps,
// each 32x64).  Both operands cp.async double-buffered.  8 K-chunks.
// ---------------------------------------------------------------------------
#define BM 128
#define BN 256
#define BK 64
#define SSTRIDE 144                 // 64 fp16 = 128 B + 16 B pad
#define A_TILE  (128 * SSTRIDE)     // 18432 B
#define B_TILE  (256 * SSTRIDE)     // 36864 B
#define A_O     0
#define B_O     A_TILE
#define BUF_B   (A_TILE + B_TILE)   // 55296 B
#define GEMM_SMEM (2 * BUF_B)       // 110592 B
#define NCHUNK  (N_FEAT / BK)       // 8

__global__ __launch_bounds__(512, 1)
void gemm_mma_kernel(const __half* __restrict__ Ah,
                     const __half* __restrict__ Bh,
                     const float* __restrict__ bias,
                     __half* __restrict__ C, int M)
{
    extern __shared__ __align__(128) char smem[];
    const uint32_t sb = smem_to_u32(smem);

    const int tid    = threadIdx.x;
    const int lane   = tid & 31;
    const int wid    = tid >> 5;          // 0..15
    const int warp_m = wid >> 2;          // 0..3  (32-row slab)
    const int warp_n = wid & 3;           // 0..3  (64-col slab)
    const int tile_row = blockIdx.x * BM;

    float acc[2][8][4];
#pragma unroll
    for (int a = 0; a < 2; a++)
#pragma unroll
        for (int b = 0; b < 8; b++)
#pragma unroll
            for (int c = 0; c < 4; c++) acc[a][b][c] = 0.f;

    // A: 128 rows x 128B = 1024 16B-slots -> 2 per thread
    // B: 256 rows x 128B = 2048 16B-slots -> 4 per thread
    auto issue = [&](int c) {
        const uint32_t base = sb + (c & 1) * BUF_B;
#pragma unroll
        for (int t = 0; t < 2; t++) {
            int idx = t * 512 + tid;          // 0..1023
            int r = idx >> 3, s = idx & 7;    // row 0..127, seg 0..7
            int gr = tile_row + r; if (gr >= M) gr = M - 1;
            cp_async16(base + A_O + r * SSTRIDE + s * 16,
                       Ah + (size_t)gr * N_FEAT + c * BK + s * 8);
        }
#pragma unroll
        for (int t = 0; t < 4; t++) {
            int idx = t * 512 + tid;          // 0..2047
            int r = idx >> 3, s = idx & 7;    // row 0..255, seg 0..7
            cp_async16(base + B_O + r * SSTRIDE + s * 16,
                       Bh + (size_t)r * N_FEAT + c * BK + s * 8);
        }
        CP_COMMIT();
    };

    auto compute = [&](int buf) {
        const uint32_t base = sb + buf * BUF_B;
        const int arow = warp_m * 32 + (lane & 15);
        const int brow = warp_n * 64 + (lane & 7) + ((lane >> 4) << 3);
#pragma unroll
        for (int kk = 0; kk < 4; kk++) {
            const int k0 = kk * 16;
            const int acol2 = (k0 + ((lane >> 4) << 3)) * 2;
            const int bcol2 = (k0 + (((lane >> 3) & 1) << 3)) * 2;
            uint32_t aF[2][4], bF[8][2];
#pragma unroll
            for (int mt = 0; mt < 2; mt++)
                ldm_x4(aF[mt], base + A_O
                       + (uint32_t)(arow + mt * 16) * SSTRIDE + acol2);
#pragma unroll
            for (int h = 0; h < 4; h++) {
                uint32_t r[4];
                ldm_x4(r, base + B_O
                       + (uint32_t)(brow + h * 16) * SSTRIDE + bcol2);
                bF[h * 2][0]     = r[0]; bF[h * 2][1]     = r[1];
                bF[h * 2 + 1][0] = r[2]; bF[h * 2 + 1][1] = r[3];
            }
#pragma unroll
            for (int mt = 0; mt < 2; mt++)
#pragma unroll
                for (int nt = 0; nt < 8; nt++)
                    mma16816(acc[mt][nt], aF[mt], bF[nt]);
        }
    };

    // ---- double-buffered pipeline ----
    issue(0);
    for (int c = 0; c < NCHUNK; c++) {
        if (c + 1 < NCHUNK) { issue(c + 1); CP_WAIT(1); }
        else                { CP_WAIT(0); }
        __syncthreads();
        compute(c & 1);
        __syncthreads();
    }

    // ---- epilogue: bias add + fp16 store ----
    const int g  = lane >> 2;
    const int tg = lane & 3;
#pragma unroll
    for (int mt = 0; mt < 2; mt++) {
        const int r0 = tile_row + warp_m * 32 + mt * 16 + g;
#pragma unroll
        for (int half = 0; half < 2; half++) {
            const int row = r0 + half * 8;
            if (row >= M) continue;
            __half* cp = C + (size_t)row * N_HID;
#pragma unroll
            for (int nt = 0; nt < 8; nt++) {
                const int col = warp_n * 64 + nt * 8 + tg * 2;
                float ox = acc[mt][nt][half * 2 + 0] + __ldg(bias + col);
                float oy = acc[mt][nt][half * 2 + 1] + __ldg(bias + col + 1);
                *(uint32_t*)(cp + col) = pack_h2(ox, oy);
            }
        }
    }
}

// ---------------------------------------------------------------------------
// ELL build: single pass.  pos = atomicAdd(cnt[r]); bucket[r*128+pos] = edge.
// ---------------------------------------------------------------------------
__global__ __launch_bounds__(256)
void ell_scatter_kernel(const int* __restrict__ rows,
                        const int* __restrict__ cols,
                        const float* __restrict__ vals, int E)
{
    int e = blockIdx.x * blockDim.x + threadIdx.x;
    if (e >= E) return;
    int r = rows[e];
    int pos = atomicAdd(&g_cnt[r], 1);
    if (pos < ELL_W)     // structurally unreachable guard
        g_eell[(size_t)r * ELL_W + pos] = make_int2(cols[e],
                                                    __float_as_int(vals[e]));
}

// ---------------------------------------------------------------------------
// Kernel C: ELL SpMM (fp16 h) + fused PReLU.  (unchanged from R11: 124 us)
// ---------------------------------------------------------------------------
__device__ __forceinline__ void stcs_v4(float* p, float4 v) {
    asm volatile("st.global.cs.v4.f32 [%0], {%1,%2,%3,%4};"
                 :: "l"(p), "f"(v.x), "f"(v.y), "f"(v.z), "f"(v.w) : "memory");
}

__device__ __forceinline__ void fma8(float4& a0, float4& a1, float v,
                                     uint4 raw)
{
    float2 f0 = h2f(raw.x), f1 = h2f(raw.y);
    float2 f2 = h2f(raw.z), f3 = h2f(raw.w);
    a0.x = fmaf(v, f0.x, a0.x); a0.y = fmaf(v, f0.y, a0.y);
    a0.z = fmaf(v, f1.x, a0.z); a0.w = fmaf(v, f1.y, a0.w);
    a1.x = fmaf(v, f2.x, a1.x); a1.y = fmaf(v, f2.y, a1.y);
    a1.z = fmaf(v, f3.x, a1.z); a1.w = fmaf(v, f3.y, a1.w);
}

__global__ __launch_bounds__(256)
void spmm_ell_prelu(float* __restrict__ out,
                    const float* __restrict__ alpha_p)
{
    const int warp = (blockIdx.x * blockDim.x + threadIdx.x) >> 5;
    const int lane = threadIdx.x & 31;
    if (warp >= N_NODES) return;

    const int len = g_cnt[warp];
    const int2* ep = g_eell + (size_t)warp * ELL_W;

    float4 acc0 = make_float4(0.f, 0.f, 0.f, 0.f);
    float4 acc1 = make_float4(0.f, 0.f, 0.f, 0.f);

    int e = 0;
    for (; e + 1 < len; e += 2) {
        int2 e0 = __ldg(&ep[e]);
        int2 e1 = __ldg(&ep[e + 1]);
        const float v0 = __int_as_float(e0.y);
        const float v1 = __int_as_float(e1.y);
        uint4 r0 = __ldg((const uint4*)(g_hh + (size_t)e0.x * N_HID) + lane);
        uint4 r1 = __ldg((const uint4*)(g_hh + (size_t)e1.x * N_HID) + lane);
        fma8(acc0, acc1, v0, r0);
        fma8(acc0, acc1, v1, r1);
    }
    if (e < len) {
        int2 e0 = __ldg(&ep[e]);
        const float v0 = __int_as_float(e0.y);
        uint4 r0 = __ldg((const uint4*)(g_hh + (size_t)e0.x * N_HID) + lane);
        fma8(acc0, acc1, v0, r0);
    }

    const float alpha = __ldg(alpha_p);
    acc0.x = acc0.x >= 0.f ? acc0.x : alpha * acc0.x;
    acc0.y = acc0.y >= 0.f ? acc0.y : alpha * acc0.y;
    acc0.z = acc0.z >= 0.f ? acc0.z : alpha * acc0.z;
    acc0.w = acc0.w >= 0.f ? acc0.w : alpha * acc0.w;
    acc1.x = acc1.x >= 0.f ? acc1.x : alpha * acc1.x;
    acc1.y = acc1.y >= 0.f ? acc1.y : alpha * acc1.y;
    acc1.z = acc1.z >= 0.f ? acc1.z : alpha * acc1.z;
    acc1.w = acc1.w >= 0.f ? acc1.w : alpha * acc1.w;

    float* dst = out + (size_t)warp * N_HID + lane * 8;
    stcs_v4(dst,     acc0);
    stcs_v4(dst + 4, acc1);
}

// ---------------------------------------------------------------------------
// Launch: fork/join — ELL build overlaps convert + GEMM chain, then SpMM.
//   main stream:  W cvt -> x cvt -> GEMM -------------.
//   side stream:  memset(cnt) -> ell_scatter -----------> join -> SpMM
// ---------------------------------------------------------------------------
extern "C" void kernel_launch(void* const* d_in, const int* in_sizes, int n_in,
                              void* d_out, int out_size)
{
    const float* x     = (const float*)d_in[0];
    const int*   rows  = (const int*)  d_in[1];
    const int*   cols  = (const int*)  d_in[2];
    const float* vals  = (const float*)d_in[3];
    const float* W     = (const float*)d_in[4];
    const float* b     = (const float*)d_in[5];
    const float* alpha = (const float*)d_in[6];

    float* out = (float*)d_out;
    const int E = in_sizes[1];

    __half *xh, *hh, *wh;
    cudaGetSymbolAddress((void**)&xh, g_xh);
    cudaGetSymbolAddress((void**)&hh, g_hh);
    cudaGetSymbolAddress((void**)&wh, g_wh);
    int* cntp;
    cudaGetSymbolAddress((void**)&cntp, g_cnt);

    cudaStream_t s1;
    cudaStreamCreateWithFlags(&s1, cudaStreamNonBlocking);
    cudaEvent_t evFork, evJoin;
    cudaEventCreateWithFlags(&evFork, cudaEventDisableTiming);
    cudaEventCreateWithFlags(&evJoin, cudaEventDisableTiming);

    // ---- fork ----
    cudaEventRecord(evFork, 0);
    cudaStreamWaitEvent(s1, evFork, 0);

    // ---- side stream: ELL build ----
    cudaMemsetAsync(cntp, 0, N_NODES * sizeof(int), s1);
    ell_scatter_kernel<<<(E + 255) / 256, 256, 0, s1>>>(rows, cols, vals, E);
    cudaEventRecord(evJoin, s1);

    // ---- main stream: converts + GEMM ----
    {
        int n4w = (N_HID * N_FEAT) / 4;
        f2h_kernel<<<(n4w + 255) / 256, 256>>>(W, wh, n4w);
        int n4x = (int)(((size_t)N_NODES * N_FEAT) / 4);
        f2h_kernel<<<(n4x + 255) / 256, 256>>>(x, xh, n4x);
    }
    cudaFuncSetAttribute(gemm_mma_kernel,
                         cudaFuncAttributeMaxDynamicSharedMemorySize, GEMM_SMEM);
    dim3 ggrid((N_NODES + BM - 1) / BM, 1);
    gemm_mma_kernel<<<ggrid, 512, GEMM_SMEM>>>(xh, wh, b, hh, N_NODES);

    // ---- join, then SpMM (needs both chains) ----
    cudaStreamWaitEvent(0, evJoin, 0);
    int nwarps_blocks = (N_NODES * 32 + 255) / 256;
    spmm_ell_prelu<<<nwarps_blocks, 256>>>(out, alpha);

    cudaEventDestroy(evFork);
    cudaEventDestroy(evJoin);
    cudaStreamDestroy(s1);
}

// round 13
// speedup vs baseline: 1.1571x; 1.1571x over previous
#include <cuda_runtime.h>
#include <cuda_bf16.h>
#include <cuda_fp16.h>
#include <cstdint>

// Problem constants (fixed by the dataset)
#define N_NODES    100000
#define N_FEAT     512
#define N_HID      256
#define ELL_W      128          // slots per row; deg ~ Poisson(32), P(overflow) < 1e-30

// ---------------------------------------------------------------------------
// Static device scratch (no allocations allowed)
// ---------------------------------------------------------------------------
__device__ __align__(16) __half g_hh[(size_t)N_NODES * N_HID];      // 51.2 MB
__device__ __align__(16) __half g_wh[(size_t)N_HID * N_FEAT];       // 256 KB
__device__ int  g_cnt[N_NODES];                                     // 400 KB
__device__ __align__(16) int2 g_eell[(size_t)N_NODES * ELL_W];      // 102.4 MB

// ---------------------------------------------------------------------------
// Baseline-PTX helpers (plain sm_80+; harness targets compute_103 w/o 'a')
// ---------------------------------------------------------------------------
__device__ __forceinline__ uint32_t smem_to_u32(const void* smem_ptr) {
    uint32_t addr;
    asm("{ .reg .u64 tmp; cvta.to.shared.u64 tmp, %1; cvt.u32.u64 %0, tmp; }"
        : "=r"(addr) : "l"(smem_ptr));
    return addr;
}

__device__ __forceinline__ void cp_async16(uint32_t saddr, const void* gptr) {
    asm volatile("cp.async.cg.shared.global [%0], [%1], 16;"
                 :: "r"(saddr), "l"(gptr));
}
#define CP_COMMIT()  asm volatile("cp.async.commit_group;")
#define CP_WAIT(N)   asm volatile("cp.async.wait_group %0;" :: "n"(N))

__device__ __forceinline__ void ldm_x4(uint32_t* r, uint32_t addr) {
    asm volatile("ldmatrix.sync.aligned.m8n8.x4.shared.b16 {%0,%1,%2,%3}, [%4];"
                 : "=r"(r[0]), "=r"(r[1]), "=r"(r[2]), "=r"(r[3]) : "r"(addr));
}

// HMMA m16n8k16 fp16 -> fp32, accumulate in place
__device__ __forceinline__ void mma16816(float* d, const uint32_t* a,
                                         const uint32_t* b) {
    asm volatile(
        "mma.sync.aligned.m16n8k16.row.col.f32.f16.f16.f32 "
        "{%0,%1,%2,%3}, {%4,%5,%6,%7}, {%8,%9}, {%0,%1,%2,%3};"
        : "+f"(d[0]), "+f"(d[1]), "+f"(d[2]), "+f"(d[3])
        : "r"(a[0]), "r"(a[1]), "r"(a[2]), "r"(a[3]),
          "r"(b[0]), "r"(b[1]));
}

__device__ __forceinline__ uint32_t pack_h2(float a, float b) {
    __half2 h = __floats2half2_rn(a, b);
    return *reinterpret_cast<uint32_t*>(&h);
}
__device__ __forceinline__ float2 h2f(uint32_t u) {
    __half2 h = *reinterpret_cast<__half2*>(&u);
    return __half22float2(h);
}

// ---------------------------------------------------------------------------
// Kernel A: W fp32 -> fp16 convert (tiny: 128K elements)
// ---------------------------------------------------------------------------
__global__ __launch_bounds__(256)
void f2h_kernel(const float* __restrict__ src, __half* __restrict__ dst,
                int n4)
{
    int i = blockIdx.x * blockDim.x + threadIdx.x;
    if (i >= n4) return;
    float4 v = ((const float4*)src)[i];
    uint2 o;
    o.x = pack_h2(v.x, v.y);
    o.y = pack_h2(v.z, v.w);
    ((uint2*)dst)[i] = o;
}

// ---------------------------------------------------------------------------
// Kernel B: fused-convert fp16 GEMM with bias, fp16 output.
// C[M,256] = half(A) * half(W)^T + bias.  Tile 64x256x32, 256 threads
// (2x4 warps, each 32x64), 2 CTAs/SM (acc only 64 regs/thread).
// A converted in-kernel (LDG fp32 -> cvt -> STS, register prefetch);
// B (W fp16) via cp.async double buffer.  A read exactly once from DRAM.
// ---------------------------------------------------------------------------
#define BM 64
#define BN 256
#define BK 32
#define SSTRIDE 80                  // smem row stride bytes (32 fp16 + pad)
#define A_TILE  (64  * SSTRIDE)     // 5120 B
#define B_TILE  (256 * SSTRIDE)     // 20480 B
#define A_O     0
#define B_O     A_TILE
#define BUF_B   (A_TILE + B_TILE)   // 25600 B
#define GEMM_SMEM (2 * BUF_B)       // 51200 B  -> 2 CTAs/SM
#define NCHUNK  (N_FEAT / BK)       // 16

__global__ __launch_bounds__(256, 2)
void gemm_mma_kernel(const float* __restrict__ A,
                     const __half* __restrict__ Bh,
                     const float* __restrict__ bias,
                     __half* __restrict__ C, int M)
{
    extern __shared__ __align__(128) char smem[];
    const uint32_t sb = smem_to_u32(smem);

    const int tid    = threadIdx.x;
    const int lane   = tid & 31;
    const int wid    = tid >> 5;
    const int warp_m = wid >> 2;          // 0..1  (32-row slab)
    const int warp_n = wid & 3;           // 0..3  (64-col slab)
    const int tile_row = blockIdx.x * BM;

    // A-load mapping: 8 threads x float4 cover one 32-float row; 2 per thread
    const int a_seg = tid & 7;            // float4 segment 0..7
    const int a_r0  = tid >> 3;           // rows a_r0 + 32*i, i=0..1

    float acc[2][8][4];
#pragma unroll
    for (int a = 0; a < 2; a++)
#pragma unroll
        for (int b = 0; b < 8; b++)
#pragma unroll
            for (int c = 0; c < 4; c++) acc[a][b][c] = 0.f;

    float4 aPre[2];

    auto ldg_a = [&](int c) {
#pragma unroll
        for (int i = 0; i < 2; i++) {
            int gr = tile_row + a_r0 + 32 * i;
            if (gr >= M) gr = M - 1;
            aPre[i] = __ldg((const float4*)(A + (size_t)gr * N_FEAT
                                            + c * BK + a_seg * 4));
        }
    };
    auto sts_a = [&](int buf) {
#pragma unroll
        for (int i = 0; i < 2; i++) {
            uint2 o;
            o.x = pack_h2(aPre[i].x, aPre[i].y);
            o.y = pack_h2(aPre[i].z, aPre[i].w);
            *(uint2*)(smem + buf * BUF_B + A_O
                      + (a_r0 + 32 * i) * SSTRIDE + a_seg * 8) = o;
        }
    };
    auto issue_b = [&](int c) {
        const uint32_t b = sb + (c & 1) * BUF_B + B_O;
#pragma unroll
        for (int t = 0; t < 4; t++) {
            int idx = t * 256 + tid;          // 0..1023
            int r = idx >> 2, s = idx & 3;    // row 0..255, 16B seg 0..3
            size_t go = (size_t)r * N_FEAT + c * BK + s * 8;
            cp_async16(b + r * SSTRIDE + s * 16, Bh + go);
        }
        CP_COMMIT();
    };

    auto compute = [&](int buf) {
        const uint32_t base = sb + buf * BUF_B;
        const int arow = warp_m * 32 + (lane & 15);
        const int brow = warp_n * 64 + (lane & 7) + ((lane >> 4) << 3);
#pragma unroll
        for (int kk = 0; kk < 2; kk++) {
            const int k0 = kk * 16;
            const int acol2 = (k0 + ((lane >> 4) << 3)) * 2;
            const int bcol2 = (k0 + (((lane >> 3) & 1) << 3)) * 2;
            uint32_t aF[2][4], bF[8][2];
#pragma unroll
            for (int mt = 0; mt < 2; mt++)
                ldm_x4(aF[mt], base + A_O
                       + (uint32_t)(arow + mt * 16) * SSTRIDE + acol2);
#pragma unroll
            for (int h = 0; h < 4; h++) {
                uint32_t r[4];
                ldm_x4(r, base + B_O
                       + (uint32_t)(brow + h * 16) * SSTRIDE + bcol2);
                bF[h * 2][0]     = r[0]; bF[h * 2][1]     = r[1];
                bF[h * 2 + 1][0] = r[2]; bF[h * 2 + 1][1] = r[3];
            }
#pragma unroll
            for (int mt = 0; mt < 2; mt++)
#pragma unroll
                for (int nt = 0; nt < 8; nt++)
                    mma16816(acc[mt][nt], aF[mt], bF[nt]);
        }
    };

    // ---- pipeline prologue ----
    ldg_a(0);
    sts_a(0);
    issue_b(0);

    for (int c = 0; c < NCHUNK; c++) {
        if (c + 1 < NCHUNK) {
            ldg_a(c + 1);           // overlap LDG latency with compute below
            issue_b(c + 1);
            CP_WAIT(1);
        } else {
            CP_WAIT(0);
        }
        __syncthreads();            // chunk c A STS + B cp.async visible
        compute(c & 1);
        __syncthreads();            // done reading buf c
        if (c + 1 < NCHUNK)
            sts_a((c + 1) & 1);     // fill other buffer's A region
    }

    // ---- epilogue: bias add + fp16 store ----
    const int g  = lane >> 2;
    const int tg = lane & 3;
#pragma unroll
    for (int mt = 0; mt < 2; mt++) {
        const int r0 = tile_row + warp_m * 32 + mt * 16 + g;
#pragma unroll
        for (int half = 0; half < 2; half++) {
            const int row = r0 + half * 8;
            if (row >= M) continue;
            __half* cp = C + (size_t)row * N_HID;
#pragma unroll
            for (int nt = 0; nt < 8; nt++) {
                const int col = warp_n * 64 + nt * 8 + tg * 2;
                float ox = acc[mt][nt][half * 2 + 0] + __ldg(bias + col);
                float oy = acc[mt][nt][half * 2 + 1] + __ldg(bias + col + 1);
                *(uint32_t*)(cp + col) = pack_h2(ox, oy);
            }
        }
    }
}

// ---------------------------------------------------------------------------
// ELL build: single pass.  pos = atomicAdd(cnt[r]); bucket[r*128+pos] = edge.
// ---------------------------------------------------------------------------
__global__ __launch_bounds__(256)
void ell_scatter_kernel(const int* __restrict__ rows,
                        const int* __restrict__ cols,
                        const float* __restrict__ vals, int E)
{
    int e = blockIdx.x * blockDim.x + threadIdx.x;
    if (e >= E) return;
    int r = rows[e];
    int pos = atomicAdd(&g_cnt[r], 1);
    if (pos < ELL_W)     // structurally unreachable guard
        g_eell[(size_t)r * ELL_W + pos] = make_int2(cols[e],
                                                    __float_as_int(vals[e]));
}

// ---------------------------------------------------------------------------
// Kernel C: ELL SpMM (fp16 h) + fused PReLU.  (unchanged: measured 124 us)
// ---------------------------------------------------------------------------
__device__ __forceinline__ void stcs_v4(float* p, float4 v) {
    asm volatile("st.global.cs.v4.f32 [%0], {%1,%2,%3,%4};"
                 :: "l"(p), "f"(v.x), "f"(v.y), "f"(v.z), "f"(v.w) : "memory");
}

__device__ __forceinline__ void fma8(float4& a0, float4& a1, float v,
                                     uint4 raw)
{
    float2 f0 = h2f(raw.x), f1 = h2f(raw.y);
    float2 f2 = h2f(raw.z), f3 = h2f(raw.w);
    a0.x = fmaf(v, f0.x, a0.x); a0.y = fmaf(v, f0.y, a0.y);
    a0.z = fmaf(v, f1.x, a0.z); a0.w = fmaf(v, f1.y, a0.w);
    a1.x = fmaf(v, f2.x, a1.x); a1.y = fmaf(v, f2.y, a1.y);
    a1.z = fmaf(v, f3.x, a1.z); a1.w = fmaf(v, f3.y, a1.w);
}

__global__ __launch_bounds__(256)
void spmm_ell_prelu(float* __restrict__ out,
                    const float* __restrict__ alpha_p)
{
    const int warp = (blockIdx.x * blockDim.x + threadIdx.x) >> 5;
    const int lane = threadIdx.x & 31;
    if (warp >= N_NODES) return;

    const int len = g_cnt[warp];
    const int2* ep = g_eell + (size_t)warp * ELL_W;

    float4 acc0 = make_float4(0.f, 0.f, 0.f, 0.f);
    float4 acc1 = make_float4(0.f, 0.f, 0.f, 0.f);

    int e = 0;
    for (; e + 1 < len; e += 2) {
        int2 e0 = __ldg(&ep[e]);
        int2 e1 = __ldg(&ep[e + 1]);
        const float v0 = __int_as_float(e0.y);
        const float v1 = __int_as_float(e1.y);
        uint4 r0 = __ldg((const uint4*)(g_hh + (size_t)e0.x * N_HID) + lane);
        uint4 r1 = __ldg((const uint4*)(g_hh + (size_t)e1.x * N_HID) + lane);
        fma8(acc0, acc1, v0, r0);
        fma8(acc0, acc1, v1, r1);
    }
    if (e < len) {
        int2 e0 = __ldg(&ep[e]);
        const float v0 = __int_as_float(e0.y);
        uint4 r0 = __ldg((const uint4*)(g_hh + (size_t)e0.x * N_HID) + lane);
        fma8(acc0, acc1, v0, r0);
    }

    const float alpha = __ldg(alpha_p);
    acc0.x = acc0.x >= 0.f ? acc0.x : alpha * acc0.x;
    acc0.y = acc0.y >= 0.f ? acc0.y : alpha * acc0.y;
    acc0.z = acc0.z >= 0.f ? acc0.z : alpha * acc0.z;
    acc0.w = acc0.w >= 0.f ? acc0.w : alpha * acc0.w;
    acc1.x = acc1.x >= 0.f ? acc1.x : alpha * acc1.x;
    acc1.y = acc1.y >= 0.f ? acc1.y : alpha * acc1.y;
    acc1.z = acc1.z >= 0.f ? acc1.z : alpha * acc1.z;
    acc1.w = acc1.w >= 0.f ? acc1.w : alpha * acc1.w;

    float* dst = out + (size_t)warp * N_HID + lane * 8;
    stcs_v4(dst,     acc0);
    stcs_v4(dst + 4, acc1);
}

// ---------------------------------------------------------------------------
// Launch: fork/join — ELL build overlaps W convert + GEMM, then SpMM.
//   main stream:  W cvt -> GEMM (fused A convert) ----.
//   side stream:  memset(cnt) -> ell_scatter -----------> join -> SpMM
// ---------------------------------------------------------------------------
extern "C" void kernel_launch(void* const* d_in, const int* in_sizes, int n_in,
                              void* d_out, int out_size)
{
    const float* x     = (const float*)d_in[0];
    const int*   rows  = (const int*)  d_in[1];
    const int*   cols  = (const int*)  d_in[2];
    const float* vals  = (const float*)d_in[3];
    const float* W     = (const float*)d_in[4];
    const float* b     = (const float*)d_in[5];
    const float* alpha = (const float*)d_in[6];

    float* out = (float*)d_out;
    const int E = in_sizes[1];

    __half *hh, *wh;
    cudaGetSymbolAddress((void**)&hh, g_hh);
    cudaGetSymbolAddress((void**)&wh, g_wh);
    int* cntp;
    cudaGetSymbolAddress((void**)&cntp, g_cnt);

    cudaStream_t s1;
    cudaStreamCreateWithFlags(&s1, cudaStreamNonBlocking);
    cudaEvent_t evFork, evJoin;
    cudaEventCreateWithFlags(&evFork, cudaEventDisableTiming);
    cudaEventCreateWithFlags(&evJoin, cudaEventDisableTiming);

    // ---- fork ----
    cudaEventRecord(evFork, 0);
    cudaStreamWaitEvent(s1, evFork, 0);

    // ---- side stream: ELL build ----
    cudaMemsetAsync(cntp, 0, N_NODES * sizeof(int), s1);
    ell_scatter_kernel<<<(E + 255) / 256, 256, 0, s1>>>(rows, cols, vals, E);
    cudaEventRecord(evJoin, s1);

    // ---- main stream: W convert + fused GEMM ----
    {
        int n4w = (N_HID * N_FEAT) / 4;
        f2h_kernel<<<(n4w + 255) / 256, 256>>>(W, wh, n4w);
    }
    cudaFuncSetAttribute(gemm_mma_kernel,
                         cudaFuncAttributeMaxDynamicSharedMemorySize, GEMM_SMEM);
    dim3 ggrid((N_NODES + BM - 1) / BM, 1);
    gemm_mma_kernel<<<ggrid, 256, GEMM_SMEM>>>(x, wh, b, hh, N_NODES);

    // ---- join, then SpMM (needs both chains) ----
    cudaStreamWaitEvent(0, evJoin, 0);
    int nwarps_blocks = (N_NODES * 32 + 255) / 256;
    spmm_ell_prelu<<<nwarps_blocks, 256>>>(out, alpha);

    cudaEventDestroy(evFork);
    cudaEventDestroy(evJoin);
    cudaStreamDestroy(s1);
}